// round 2
// baseline (speedup 1.0000x reference)
#include <cuda_runtime.h>

#define NI 2000      // inner tree nodes
#define NL 10000     // leaves / vocab
#define ND 128       // docs
#define PP 2048      // padded proj width
#define TI 64        // doc tile
#define FC 64        // feature chunk
#define SROW 68      // padded shared row stride (words), keeps float4 align + dealigns banks
#define NCHUNK (PP / FC + (NL + FC - 1) / FC)   // 32 + 157 = 189
#define GY 95        // grid.y for k_pair; each block loops chunks y, y+95

__device__ unsigned long long g_amax[NL];
__device__ float g_proj[ND * PP];

// ---------------------------------------------------------------- init
__global__ void k_init(float* __restrict__ out) {
    int i = blockIdx.x * blockDim.x + threadIdx.x;
    if (i < NL) g_amax[i] = 0ull;
    if (i < ND * ND) out[i] = 0.0f;
}

// ---------------------------------------------------------------- column argmax of param
// grid (40, 10): 256 cols/block, 200-row chunks. Coalesced row-major reads.
__global__ void k_argmax(const float* __restrict__ param) {
    int j = blockIdx.x * blockDim.x + threadIdx.x;
    if (j >= NL) return;
    const int CHUNK = NI / 10;                 // 200
    int r0 = blockIdx.y * CHUNK;
    const float* p = param + (size_t)r0 * NL + j;
    float best = p[0];
    int bidx = r0;
    #pragma unroll 4
    for (int r = 1; r < CHUNK; r++) {
        float v = p[(size_t)r * NL];
        if (v > best) { best = v; bidx = r0 + r; }
    }
    // order-preserving float->uint, pack with row idx for deterministic merge
    unsigned u = __float_as_uint(best);
    u = (u & 0x80000000u) ? ~u : (u | 0x80000000u);
    unsigned long long key = ((unsigned long long)u << 32) | (unsigned)bidx;
    atomicMax(&g_amax[j], key);
}

// ---------------------------------------------------------------- proj = subtree sums of argmax-scattered mass
// one block per doc
__global__ void k_proj(const float* __restrict__ mass) {
    __shared__ float s[NI];
    int d = blockIdx.x, t = threadIdx.x;
    for (int i = t; i < NI; i += blockDim.x) s[i] = 0.0f;
    __syncthreads();
    const float* m = mass + (size_t)d * NL;
    for (int j = t; j < NL; j += blockDim.x) {
        int a = (int)(unsigned)(g_amax[j] & 0xFFFFFFFFull);
        atomicAdd(&s[a], m[j]);
    }
    __syncthreads();
    // bottom-up over tree levels: parents {156..399},{31..155},{6..30},{1..5},{0}
    const int lo[5] = {156, 31, 6, 1, 0};
    const int hi[5] = {399, 155, 30, 5, 0};
    for (int L = 0; L < 5; L++) {
        for (int p = lo[L] + t; p <= hi[L]; p += blockDim.x) {
            float acc = s[p];
            int c0 = 5 * p + 1;
            #pragma unroll
            for (int c = 0; c < 5; c++)
                if (c0 + c < NI) acc += s[c0 + c];
            s[p] = acc;
        }
        __syncthreads();
    }
    float* gp = g_proj + (size_t)d * PP;
    for (int i = t; i < PP; i += blockDim.x)
        gp[i] = (i < NI) ? s[i] : 0.0f;
}

// ---------------------------------------------------------------- pairwise L1 over [proj | mass]
// blockIdx.x: tile-pair 0:(0,0) 1:(0,1) 2:(1,1) over 64-doc tiles (symmetry).
// blockIdx.y: base feature chunk; block loops chunks y, y+GY.
// Shared is feature-major: sa[f][row] so a 4-row slab is one float4 (2 LDS.128 / f / thread).
__global__ void k_pair(const float* __restrict__ mass, float* __restrict__ out) {
    __shared__ float sa[FC * SROW];
    __shared__ float sb[FC * SROW];
    int tp = blockIdx.x;
    int it = (tp == 2) ? 1 : 0;
    int jt = (tp == 0) ? 0 : 1;
    int tid = threadIdx.x;
    int tx = tid & 15, ty = tid >> 4;

    float acc[4][4];
    #pragma unroll
    for (int r = 0; r < 4; r++)
        #pragma unroll
        for (int c = 0; c < 4; c++) acc[r][c] = 0.0f;

    for (int chunk = blockIdx.y; chunk < NCHUNK; chunk += GY) {
        const float* base;
        int fb, stride, nval;
        if (chunk < PP / FC) { base = g_proj; fb = chunk * FC; stride = PP; nval = FC; }
        else { base = mass; fb = (chunk - PP / FC) * FC; stride = NL; nval = min(FC, NL - fb); }

        __syncthreads();   // shared reuse barrier
        #pragma unroll
        for (int k = 0; k < 16; k++) {
            int idx = tid + k * 256;         // 0..4095
            int f = idx & (FC - 1);          // consecutive tid -> consecutive f (coalesced gmem)
            int row = idx >> 6;              // 0..63
            float va = 0.0f, vb = 0.0f;
            if (f < nval) {
                va = base[(size_t)(it * TI + row) * stride + fb + f];
                vb = base[(size_t)(jt * TI + row) * stride + fb + f];
            }
            sa[f * SROW + row] = va;
            sb[f * SROW + row] = vb;
        }
        __syncthreads();

        #pragma unroll 8
        for (int f = 0; f < FC; f++) {
            float4 a = *(const float4*)&sa[f * SROW + ty * 4];
            float4 b = *(const float4*)&sb[f * SROW + tx * 4];
            float ar[4] = {a.x, a.y, a.z, a.w};
            float br[4] = {b.x, b.y, b.z, b.w};
            #pragma unroll
            for (int r = 0; r < 4; r++)
                #pragma unroll
                for (int c = 0; c < 4; c++)
                    acc[r][c] += fabsf(ar[r] - br[c]);
        }
    }

    int ib = it * TI + ty * 4, jb = jt * TI + tx * 4;
    #pragma unroll
    for (int r = 0; r < 4; r++)
        #pragma unroll
        for (int c = 0; c < 4; c++) {
            atomicAdd(&out[(ib + r) * ND + (jb + c)], acc[r][c]);
            if (tp == 1)   // off-diagonal tile-pair: mirror into lower triangle
                atomicAdd(&out[(jb + c) * ND + (ib + r)], acc[r][c]);
        }
}

// ---------------------------------------------------------------- launch
extern "C" void kernel_launch(void* const* d_in, const int* in_sizes, int n_in,
                              void* d_out, int out_size) {
    const float* mass  = (const float*)d_in[0];   // (128, 10000) f32
    const float* param = (const float*)d_in[1];   // (2000, 10000) f32
    float* out = (float*)d_out;                   // (128, 128) f32

    k_init<<<(ND * ND + 255) / 256, 256>>>(out);
    k_argmax<<<dim3((NL + 255) / 256, 10), 256>>>(param);
    k_proj<<<ND, 256>>>(mass);
    k_pair<<<dim3(3, GY), 256>>>(mass, out);
}

// round 3
// speedup vs baseline: 1.4404x; 1.4404x over previous
#include <cuda_runtime.h>

#define NI 2000      // inner tree nodes
#define NL 10000     // leaves / vocab
#define ND 128       // docs
#define PP 2048      // padded proj width
#define TI 64        // doc tile
#define FC 64        // feature chunk
#define SROW 68      // padded shared row stride (float4-aligned, bank-skewed)
#define NMASS_CH 157 // ceil(NL/FC)
#define NPROJ_CH 32  // PP/FC
#define AG_BLKS 800  // argmax blocks: 40 col-blocks x 20 row-chunks
#define AG_CH 100    // rows per argmax chunk
#define PPAIR_BLKS 96

__device__ unsigned long long g_amax[NL];
__device__ float g_proj[ND * PP];
__device__ float g_S[ND];

// ---------------------------------------------------------------- init
__global__ void k_init(float* __restrict__ out) {
    int i = blockIdx.x * blockDim.x + threadIdx.x;
    if (i < NL) g_amax[i] = 0ull;
    if (i < ND * ND) out[i] = 0.0f;
    if (i < ND) g_S[i] = 0.0f;
}

// ---------------------------------------------------------------- shared pair-tile worker
// min-trick: accumulates Sum_f min(a,b) for a 64x64 doc tile over one 64-feature
// chunk, then atomically adds -2*acc into out. tp: 0=(0,0) 1=(0,1)+mirror 2=(1,1).
__device__ __forceinline__ void pair_tile(
    const float* __restrict__ base, int stride, int fb, int nval,
    int tp, float* __restrict__ out, float* sa, float* sb)
{
    int it = (tp == 2) ? 1 : 0;
    int jt = (tp == 0) ? 0 : 1;
    int tid = threadIdx.x;
    int tx = tid & 15, ty = tid >> 4;

    float acc[4][4];
    #pragma unroll
    for (int r = 0; r < 4; r++)
        #pragma unroll
        for (int c = 0; c < 4; c++) acc[r][c] = 0.0f;

    // feature-major shared fill: consecutive tid -> consecutive f (coalesced gmem)
    #pragma unroll
    for (int k = 0; k < 16; k++) {
        int idx = tid + k * 256;         // 0..4095
        int f = idx & (FC - 1);
        int row = idx >> 6;              // 0..63
        float va = 0.0f, vb = 0.0f;
        if (f < nval) {
            va = base[(size_t)(it * TI + row) * stride + fb + f];
            vb = base[(size_t)(jt * TI + row) * stride + fb + f];
        }
        sa[f * SROW + row] = va;
        sb[f * SROW + row] = vb;
    }
    __syncthreads();

    #pragma unroll 8
    for (int f = 0; f < FC; f++) {
        float4 a = *(const float4*)&sa[f * SROW + ty * 4];
        float4 b = *(const float4*)&sb[f * SROW + tx * 4];
        float ar[4] = {a.x, a.y, a.z, a.w};
        float br[4] = {b.x, b.y, b.z, b.w};
        #pragma unroll
        for (int r = 0; r < 4; r++)
            #pragma unroll
            for (int c = 0; c < 4; c++)
                acc[r][c] += fminf(ar[r], br[c]);   // FMNMX(alu) + FADD(fma)
    }

    int ib = it * TI + ty * 4, jb = jt * TI + tx * 4;
    #pragma unroll
    for (int r = 0; r < 4; r++)
        #pragma unroll
        for (int c = 0; c < 4; c++) {
            float v = -2.0f * acc[r][c];
            atomicAdd(&out[(ib + r) * ND + (jb + c)], v);
            if (tp == 1)
                atomicAdd(&out[(jb + c) * ND + (ib + r)], v);
        }
}

// ---------------------------------------------------------------- fused: argmax || mass-pair
// argmax blocks are DRAM-bound (pipes idle), mass-pair blocks are pipe-bound
// (DRAM idle). They are independent -> overlap inside one launch.
__global__ void __launch_bounds__(256)
k_fused1(const float* __restrict__ mass, const float* __restrict__ param,
         float* __restrict__ out) {
    __shared__ float sa[FC * SROW];
    __shared__ float sb[FC * SROW];

    if (blockIdx.x < AG_BLKS) {
        // ---- column argmax of param, 4 independent chains for MLP ----
        int bid = blockIdx.x;
        int j = (bid % 40) * 256 + threadIdx.x;
        if (j >= NL) return;
        int r0 = (bid / 40) * AG_CH;
        const float* p = param + (size_t)r0 * NL + j;
        float b0 = -3.4e38f, b1 = -3.4e38f, b2 = -3.4e38f, b3 = -3.4e38f;
        int i0 = 0, i1 = 1, i2 = 2, i3 = 3;
        #pragma unroll 2
        for (int r = 0; r < AG_CH; r += 4) {
            float v0 = p[(size_t)(r + 0) * NL];
            float v1 = p[(size_t)(r + 1) * NL];
            float v2 = p[(size_t)(r + 2) * NL];
            float v3 = p[(size_t)(r + 3) * NL];
            if (v0 > b0) { b0 = v0; i0 = r; }
            if (v1 > b1) { b1 = v1; i1 = r + 1; }
            if (v2 > b2) { b2 = v2; i2 = r + 2; }
            if (v3 > b3) { b3 = v3; i3 = r + 3; }
        }
        float best = b0; int bi = i0;
        if (b1 > best) { best = b1; bi = i1; }
        if (b2 > best) { best = b2; bi = i2; }
        if (b3 > best) { best = b3; bi = i3; }
        bi += r0;
        unsigned u = __float_as_uint(best);
        u = (u & 0x80000000u) ? ~u : (u | 0x80000000u);
        unsigned long long key = ((unsigned long long)u << 32) | (unsigned)bi;
        atomicMax(&g_amax[j], key);
    } else {
        // ---- mass pair blocks: one 64-feature chunk, one tile-pair each ----
        int pid = blockIdx.x - AG_BLKS;   // 0..470
        int tp = pid % 3;
        int chunk = pid / 3;              // 0..156
        int fb = chunk * FC;
        int nval = min(FC, NL - fb);
        pair_tile(mass, NL, fb, nval, tp, out, sa, sb);
    }
}

// ---------------------------------------------------------------- proj = subtree sums, plus S[d]
__global__ void k_proj(const float* __restrict__ mass) {
    __shared__ float s[NI];
    __shared__ float red[256];
    int d = blockIdx.x, t = threadIdx.x;
    for (int i = t; i < NI; i += 256) s[i] = 0.0f;
    __syncthreads();
    const float* m = mass + (size_t)d * NL;
    float msum = 0.0f;
    for (int j = t; j < NL; j += 256) {
        float v = m[j];
        msum += v;
        int a = (int)(unsigned)(g_amax[j] & 0xFFFFFFFFull);
        atomicAdd(&s[a], v);
    }
    __syncthreads();
    // bottom-up tree levels: parents {156..399},{31..155},{6..30},{1..5},{0}
    const int lo[5] = {156, 31, 6, 1, 0};
    const int hi[5] = {399, 155, 30, 5, 0};
    for (int L = 0; L < 5; L++) {
        for (int p = lo[L] + t; p <= hi[L]; p += 256) {
            float acc = s[p];
            int c0 = 5 * p + 1;
            #pragma unroll
            for (int c = 0; c < 5; c++)
                if (c0 + c < NI) acc += s[c0 + c];
            s[p] = acc;
        }
        __syncthreads();
    }
    // S[d] = sum(proj) + sum(mass)
    float psum = 0.0f;
    for (int i = t; i < NI; i += 256) psum += s[i];
    red[t] = msum + psum;
    __syncthreads();
    for (int w = 128; w > 0; w >>= 1) {
        if (t < w) red[t] += red[t + w];
        __syncthreads();
    }
    if (t == 0) g_S[d] = red[0];
    float* gp = g_proj + (size_t)d * PP;
    for (int i = t; i < PP; i += 256)
        gp[i] = (i < NI) ? s[i] : 0.0f;
}

// ---------------------------------------------------------------- fused: proj-pair || S epilogue
__global__ void __launch_bounds__(256)
k_fused2(float* __restrict__ out) {
    __shared__ float sa[FC * SROW];
    __shared__ float sb[FC * SROW];
    if (blockIdx.x < PPAIR_BLKS) {
        int pid = blockIdx.x;
        pair_tile(g_proj, PP, (pid / 3) * FC, FC, pid % 3, out, sa, sb);
    } else {
        int e = (blockIdx.x - PPAIR_BLKS) * 256 + threadIdx.x;  // 0..16383
        atomicAdd(&out[e], g_S[e >> 7] + g_S[e & 127]);
    }
}

// ---------------------------------------------------------------- launch
extern "C" void kernel_launch(void* const* d_in, const int* in_sizes, int n_in,
                              void* d_out, int out_size) {
    const float* mass  = (const float*)d_in[0];   // (128, 10000) f32
    const float* param = (const float*)d_in[1];   // (2000, 10000) f32
    float* out = (float*)d_out;                   // (128, 128) f32

    k_init<<<(ND * ND + 255) / 256, 256>>>(out);
    k_fused1<<<AG_BLKS + 3 * NMASS_CH, 256>>>(mass, param, out);
    k_proj<<<ND, 256>>>(mass);
    k_fused2<<<PPAIR_BLKS + (ND * ND) / 256, 256>>>(out);
}

// round 4
// speedup vs baseline: 1.7241x; 1.1970x over previous
#include <cuda_runtime.h>
#include <cuda_fp16.h>

#define NI 2000      // inner tree nodes
#define NL 10000     // leaves / vocab
#define ND 128       // docs
#define PP 2048      // padded proj width
#define FC 64        // feature chunk
#define NMASS_CH 157 // ceil(NL/FC)
#define AG_BLKS 800  // argmax: 40 col-blocks x 20 row-chunks
#define AG_CH 100    // rows per argmax chunk
#define MP_BLKS (3 * NMASS_CH)   // 471 mass-pair blocks
#define SROWH 68     // half2 row stride per feature-pair (16B-aligned, skewed)
// fused2: proj pairs on 32-doc tiles
#define PT 32
#define PSROW 36
#define NPP 10       // tile-pairs among 4 tiles of 32
#define PP_BLKS (NPP * (PP / FC))   // 320

__device__ unsigned long long g_amax[NL];
__device__ float g_proj[ND * PP];
__device__ float g_S[ND];

__constant__ int c_it[NPP] = {0,0,0,0,1,1,1,2,2,3};
__constant__ int c_jt[NPP] = {0,1,2,3,1,2,3,2,3,3};

__device__ __forceinline__ __half2 u2h2(unsigned u) {
    return *reinterpret_cast<__half2*>(&u);
}

// ---------------------------------------------------------------- init
__global__ void k_init(float* __restrict__ out) {
    int i = blockIdx.x * blockDim.x + threadIdx.x;
    if (i < NL) g_amax[i] = 0ull;
    if (i < ND * ND) out[i] = 0.0f;
    if (i < ND) g_S[i] = 0.0f;
}

// ---------------------------------------------------------------- fused: argmax || fp16 mass-pair
__global__ void __launch_bounds__(256)
k_fused1(const float* __restrict__ mass, const float* __restrict__ param,
         float* __restrict__ out) {
    __shared__ __half2 sa2[32 * SROWH];
    __shared__ __half2 sb2[32 * SROWH];

    if (blockIdx.x < AG_BLKS) {
        // ---- column argmax of param, 4 independent chains for MLP ----
        int bid = blockIdx.x;
        int j = (bid % 40) * 256 + threadIdx.x;
        if (j >= NL) return;
        int r0 = (bid / 40) * AG_CH;
        const float* p = param + (size_t)r0 * NL + j;
        float b0 = -3.4e38f, b1 = -3.4e38f, b2 = -3.4e38f, b3 = -3.4e38f;
        int i0 = 0, i1 = 1, i2 = 2, i3 = 3;
        #pragma unroll 2
        for (int r = 0; r < AG_CH; r += 4) {
            float v0 = p[(size_t)(r + 0) * NL];
            float v1 = p[(size_t)(r + 1) * NL];
            float v2 = p[(size_t)(r + 2) * NL];
            float v3 = p[(size_t)(r + 3) * NL];
            if (v0 > b0) { b0 = v0; i0 = r; }
            if (v1 > b1) { b1 = v1; i1 = r + 1; }
            if (v2 > b2) { b2 = v2; i2 = r + 2; }
            if (v3 > b3) { b3 = v3; i3 = r + 3; }
        }
        float best = b0; int bi = i0;
        if (b1 > best) { best = b1; bi = i1; }
        if (b2 > best) { best = b2; bi = i2; }
        if (b3 > best) { best = b3; bi = i3; }
        bi += r0;
        unsigned u = __float_as_uint(best);
        u = (u & 0x80000000u) ? ~u : (u | 0x80000000u);
        unsigned long long key = ((unsigned long long)u << 32) | (unsigned)bi;
        atomicMax(&g_amax[j], key);
    } else {
        // ---- fp16 mass-pair: one 64-feature chunk, one 64x64 tile-pair ----
        int pid = blockIdx.x - AG_BLKS;
        int tp = pid % 3;                 // 0:(0,0) 1:(0,1)+mirror 2:(1,1)
        int chunk = pid / 3;
        int fb = chunk * FC;
        int nh = min(FC, NL - fb) >> 1;   // valid half2 feature-pairs (nval even)
        int it = (tp == 2) ? 1 : 0;
        int jt = (tp == 0) ? 0 : 1;
        int tid = threadIdx.x;

        const __half2 hz = __float2half2_rn(0.0f);
        #pragma unroll
        for (int k = 0; k < 8; k++) {
            int idx = tid + k * 256;          // 0..2047
            int f2 = idx & 31;                // feature-pair: coalesced gmem
            int row = idx >> 5;               // 0..63
            __half2 ha = hz, hb = hz;
            if (f2 < nh) {
                float2 va = *(const float2*)&mass[(size_t)(it * 64 + row) * NL + fb + 2 * f2];
                float2 vb = *(const float2*)&mass[(size_t)(jt * 64 + row) * NL + fb + 2 * f2];
                ha = __floats2half2_rn(va.x, va.y);
                hb = __floats2half2_rn(vb.x, vb.y);
            }
            sa2[f2 * SROWH + row] = ha;
            sb2[f2 * SROWH + row] = hb;
        }
        __syncthreads();

        int tx = tid & 15, ty = tid >> 4;
        __half2 acc[4][4];
        #pragma unroll
        for (int r = 0; r < 4; r++)
            #pragma unroll
            for (int c = 0; c < 4; c++) acc[r][c] = hz;

        #pragma unroll 4
        for (int f2 = 0; f2 < 32; f2++) {
            uint4 ua = *(const uint4*)&sa2[f2 * SROWH + ty * 4];
            uint4 ub = *(const uint4*)&sb2[f2 * SROWH + tx * 4];
            __half2 ar[4] = {u2h2(ua.x), u2h2(ua.y), u2h2(ua.z), u2h2(ua.w)};
            __half2 br[4] = {u2h2(ub.x), u2h2(ub.y), u2h2(ub.z), u2h2(ub.w)};
            #pragma unroll
            for (int r = 0; r < 4; r++)
                #pragma unroll
                for (int c = 0; c < 4; c++)
                    acc[r][c] = __hadd2(acc[r][c], __hmin2(ar[r], br[c]));
        }

        int ib = it * 64 + ty * 4, jb = jt * 64 + tx * 4;
        #pragma unroll
        for (int r = 0; r < 4; r++)
            #pragma unroll
            for (int c = 0; c < 4; c++) {
                float2 f = __half22float2(acc[r][c]);
                float v = -2.0f * (f.x + f.y);
                atomicAdd(&out[(ib + r) * ND + (jb + c)], v);
                if (tp == 1)
                    atomicAdd(&out[(jb + c) * ND + (ib + r)], v);
            }
    }
}

// ---------------------------------------------------------------- proj = subtree sums, plus S[d]
__global__ void __launch_bounds__(512)
k_proj(const float* __restrict__ mass) {
    __shared__ float s[NI];
    __shared__ float red[512];
    int d = blockIdx.x, t = threadIdx.x;
    for (int i = t; i < NI; i += 512) s[i] = 0.0f;
    __syncthreads();
    const float* m = mass + (size_t)d * NL;
    float msum = 0.0f;
    for (int j = t; j < NL; j += 512) {
        float v = m[j];
        msum += v;
        int a = (int)(unsigned)(g_amax[j] & 0xFFFFFFFFull);
        atomicAdd(&s[a], v);
    }
    __syncthreads();
    // bottom-up tree levels: parents {156..399},{31..155},{6..30},{1..5},{0}
    const int lo[5] = {156, 31, 6, 1, 0};
    const int hi[5] = {399, 155, 30, 5, 0};
    for (int L = 0; L < 5; L++) {
        for (int p = lo[L] + t; p <= hi[L]; p += 512) {
            float acc = s[p];
            int c0 = 5 * p + 1;
            #pragma unroll
            for (int c = 0; c < 5; c++)
                if (c0 + c < NI) acc += s[c0 + c];
            s[p] = acc;
        }
        __syncthreads();
    }
    float psum = 0.0f;
    for (int i = t; i < NI; i += 512) psum += s[i];
    red[t] = msum + psum;
    __syncthreads();
    for (int w = 256; w > 0; w >>= 1) {
        if (t < w) red[t] += red[t + w];
        __syncthreads();
    }
    if (t == 0) g_S[d] = red[0];
    float* gp = g_proj + (size_t)d * PP;
    for (int i = t; i < PP; i += 512)
        gp[i] = (i < NI) ? s[i] : 0.0f;
}

// ---------------------------------------------------------------- fused: fp32 proj-pair (32-tiles) || S epilogue
__global__ void __launch_bounds__(256)
k_fused2(float* __restrict__ out) {
    __shared__ float sa[FC * PSROW];
    __shared__ float sb[FC * PSROW];
    if (blockIdx.x < PP_BLKS) {
        int pid = blockIdx.x;
        int tp = pid % NPP;
        int fb = (pid / NPP) * FC;
        int it = c_it[tp], jt = c_jt[tp];
        int tid = threadIdx.x;

        #pragma unroll
        for (int k = 0; k < 8; k++) {
            int idx = tid + k * 256;          // 0..2047
            int f = idx & 63;
            int row = idx >> 6;               // 0..31
            sa[f * PSROW + row] = g_proj[(size_t)(it * PT + row) * PP + fb + f];
            sb[f * PSROW + row] = g_proj[(size_t)(jt * PT + row) * PP + fb + f];
        }
        __syncthreads();

        int tx = tid & 15, ty = tid >> 4;
        float acc[2][2] = {{0.f, 0.f}, {0.f, 0.f}};
        #pragma unroll 8
        for (int f = 0; f < FC; f++) {
            float2 a = *(const float2*)&sa[f * PSROW + ty * 2];
            float2 b = *(const float2*)&sb[f * PSROW + tx * 2];
            acc[0][0] += fminf(a.x, b.x);
            acc[0][1] += fminf(a.x, b.y);
            acc[1][0] += fminf(a.y, b.x);
            acc[1][1] += fminf(a.y, b.y);
        }

        int ib = it * PT + ty * 2, jb = jt * PT + tx * 2;
        #pragma unroll
        for (int r = 0; r < 2; r++)
            #pragma unroll
            for (int c = 0; c < 2; c++) {
                float v = -2.0f * acc[r][c];
                atomicAdd(&out[(ib + r) * ND + (jb + c)], v);
                if (it != jt)
                    atomicAdd(&out[(jb + c) * ND + (ib + r)], v);
            }
    } else {
        int e = (blockIdx.x - PP_BLKS) * 256 + threadIdx.x;  // 0..16383
        atomicAdd(&out[e], g_S[e >> 7] + g_S[e & 127]);
    }
}

// ---------------------------------------------------------------- launch
extern "C" void kernel_launch(void* const* d_in, const int* in_sizes, int n_in,
                              void* d_out, int out_size) {
    const float* mass  = (const float*)d_in[0];   // (128, 10000) f32
    const float* param = (const float*)d_in[1];   // (2000, 10000) f32
    float* out = (float*)d_out;                   // (128, 128) f32

    k_init<<<(ND * ND + 255) / 256, 256>>>(out);
    k_fused1<<<AG_BLKS + MP_BLKS, 256>>>(mass, param, out);
    k_proj<<<ND, 512>>>(mass);
    k_fused2<<<PP_BLKS + (ND * ND) / 256, 256>>>(out);
}

// round 5
// speedup vs baseline: 1.8471x; 1.0713x over previous
#include <cuda_runtime.h>
#include <cuda_fp16.h>

#define NI 2000      // inner tree nodes
#define NL 10000     // leaves / vocab
#define ND 128       // docs
#define PP 2048      // padded proj width
#define FC 64        // mass feature chunk
#define NMASS_CH 157 // ceil(NL/FC)
#define AG_BLKS 200  // argmax: 10 col-blocks (float4) x 20 row-chunks
#define AG_CH 100    // rows per argmax chunk
#define MP_BLKS (3 * NMASS_CH)   // 471 mass-pair blocks
#define SROWH 68     // half2 row stride per feature-pair
// fused2: proj pairs on 32-doc tiles, 32-feature chunks
#define PT 32
#define PFC 32
#define PSROW 34     // float2-aligned, bank-skewed
#define NPP 10       // tile-pairs among 4 tiles of 32 docs
#define PP_BLKS (NPP * (PP / PFC))   // 640

__device__ unsigned long long g_amax[NL];
__device__ float g_proj[ND * PP];
__device__ float g_S[ND];

__constant__ int c_it[NPP] = {0,0,0,0,1,1,1,2,2,3};
__constant__ int c_jt[NPP] = {0,1,2,3,1,2,3,2,3,3};

__device__ __forceinline__ __half2 u2h2(unsigned u) {
    return *reinterpret_cast<__half2*>(&u);
}
__device__ __forceinline__ unsigned long long pack_key(float v, int idx) {
    unsigned u = __float_as_uint(v);
    u = (u & 0x80000000u) ? ~u : (u | 0x80000000u);
    return ((unsigned long long)u << 32) | (unsigned)idx;
}

// ---------------------------------------------------------------- init
__global__ void k_init(float* __restrict__ out) {
    int i = blockIdx.x * blockDim.x + threadIdx.x;
    if (i < NL) g_amax[i] = 0ull;
    if (i < ND * ND) out[i] = 0.0f;
    if (i < ND) g_S[i] = 0.0f;
}

// ---------------------------------------------------------------- fused: float4 argmax || fp16 mass-pair
__global__ void __launch_bounds__(256)
k_fused1(const float* __restrict__ mass, const float* __restrict__ param,
         float* __restrict__ out) {
    __shared__ __half2 sa2[32 * SROWH];
    __shared__ __half2 sb2[32 * SROWH];

    if (blockIdx.x < AG_BLKS) {
        // ---- column argmax of param: float4 loads, 4 lane-chains ----
        int bid = blockIdx.x;
        int j4 = (bid % 10) * 256 + threadIdx.x;    // float4 column
        if (j4 >= NL / 4) return;
        int r0 = (bid / 10) * AG_CH;
        const float4* p = (const float4*)param + (size_t)r0 * (NL / 4) + j4;
        float4 bv = p[0];
        int ix = r0, iy = r0, iz = r0, iw = r0;
        #pragma unroll 4
        for (int r = 1; r < AG_CH; r++) {
            float4 v = p[(size_t)r * (NL / 4)];
            if (v.x > bv.x) { bv.x = v.x; ix = r0 + r; }
            if (v.y > bv.y) { bv.y = v.y; iy = r0 + r; }
            if (v.z > bv.z) { bv.z = v.z; iz = r0 + r; }
            if (v.w > bv.w) { bv.w = v.w; iw = r0 + r; }
        }
        int j = 4 * j4;
        atomicMax(&g_amax[j + 0], pack_key(bv.x, ix));
        atomicMax(&g_amax[j + 1], pack_key(bv.y, iy));
        atomicMax(&g_amax[j + 2], pack_key(bv.z, iz));
        atomicMax(&g_amax[j + 3], pack_key(bv.w, iw));
    } else {
        // ---- fp16 mass-pair: one 64-feature chunk, one 64x64 tile-pair ----
        int pid = blockIdx.x - AG_BLKS;
        int tp = pid % 3;                 // 0:(0,0) 1:(0,1)+mirror 2:(1,1)
        int chunk = pid / 3;
        int fb = chunk * FC;
        int nh = min(FC, NL - fb) >> 1;   // valid half2 feature-pairs
        int it = (tp == 2) ? 1 : 0;
        int jt = (tp == 0) ? 0 : 1;
        int tid = threadIdx.x;

        const __half2 hz = __float2half2_rn(0.0f);
        #pragma unroll
        for (int k = 0; k < 8; k++) {
            int idx = tid + k * 256;          // 0..2047
            int f2 = idx & 31;
            int row = idx >> 5;               // 0..63
            __half2 ha = hz, hb = hz;
            if (f2 < nh) {
                float2 va = *(const float2*)&mass[(size_t)(it * 64 + row) * NL + fb + 2 * f2];
                float2 vb = *(const float2*)&mass[(size_t)(jt * 64 + row) * NL + fb + 2 * f2];
                ha = __floats2half2_rn(va.x, va.y);
                hb = __floats2half2_rn(vb.x, vb.y);
            }
            sa2[f2 * SROWH + row] = ha;
            sb2[f2 * SROWH + row] = hb;
        }
        __syncthreads();

        int tx = tid & 15, ty = tid >> 4;
        __half2 acc[4][4];
        #pragma unroll
        for (int r = 0; r < 4; r++)
            #pragma unroll
            for (int c = 0; c < 4; c++) acc[r][c] = hz;

        #pragma unroll 4
        for (int f2 = 0; f2 < 32; f2++) {
            uint4 ua = *(const uint4*)&sa2[f2 * SROWH + ty * 4];
            uint4 ub = *(const uint4*)&sb2[f2 * SROWH + tx * 4];
            __half2 ar[4] = {u2h2(ua.x), u2h2(ua.y), u2h2(ua.z), u2h2(ua.w)};
            __half2 br[4] = {u2h2(ub.x), u2h2(ub.y), u2h2(ub.z), u2h2(ub.w)};
            #pragma unroll
            for (int r = 0; r < 4; r++)
                #pragma unroll
                for (int c = 0; c < 4; c++)
                    acc[r][c] = __hadd2(acc[r][c], __hmin2(ar[r], br[c]));
        }

        int ib = it * 64 + ty * 4, jb = jt * 64 + tx * 4;
        #pragma unroll
        for (int r = 0; r < 4; r++)
            #pragma unroll
            for (int c = 0; c < 4; c++) {
                float2 f = __half22float2(acc[r][c]);
                float v = -2.0f * (f.x + f.y);
                atomicAdd(&out[(ib + r) * ND + (jb + c)], v);
                if (tp == 1)
                    atomicAdd(&out[(jb + c) * ND + (ib + r)], v);
            }
    }
}

// ---------------------------------------------------------------- proj = subtree sums, plus S[d]
__global__ void __launch_bounds__(512)
k_proj(const float* __restrict__ mass) {
    __shared__ float s[NI];
    __shared__ float red[512];
    int d = blockIdx.x, t = threadIdx.x;
    for (int i = t; i < NI; i += 512) s[i] = 0.0f;
    __syncthreads();
    const float4* m4 = (const float4*)(mass + (size_t)d * NL);
    float msum = 0.0f;
    for (int j4 = t; j4 < NL / 4; j4 += 512) {
        float4 v = m4[j4];
        msum += v.x + v.y + v.z + v.w;
        int a0 = (int)(unsigned)(__ldg(&g_amax[4 * j4 + 0]) & 0xFFFFFFFFull);
        int a1 = (int)(unsigned)(__ldg(&g_amax[4 * j4 + 1]) & 0xFFFFFFFFull);
        int a2 = (int)(unsigned)(__ldg(&g_amax[4 * j4 + 2]) & 0xFFFFFFFFull);
        int a3 = (int)(unsigned)(__ldg(&g_amax[4 * j4 + 3]) & 0xFFFFFFFFull);
        atomicAdd(&s[a0], v.x);
        atomicAdd(&s[a1], v.y);
        atomicAdd(&s[a2], v.z);
        atomicAdd(&s[a3], v.w);
    }
    __syncthreads();
    // bottom-up tree levels: parents {156..399},{31..155},{6..30},{1..5},{0}
    const int lo[5] = {156, 31, 6, 1, 0};
    const int hi[5] = {399, 155, 30, 5, 0};
    for (int L = 0; L < 5; L++) {
        for (int p = lo[L] + t; p <= hi[L]; p += 512) {
            float acc = s[p];
            int c0 = 5 * p + 1;
            #pragma unroll
            for (int c = 0; c < 5; c++)
                if (c0 + c < NI) acc += s[c0 + c];
            s[p] = acc;
        }
        __syncthreads();
    }
    float psum = 0.0f;
    for (int i = t; i < NI; i += 512) psum += s[i];
    red[t] = msum + psum;
    __syncthreads();
    for (int w = 256; w > 0; w >>= 1) {
        if (t < w) red[t] += red[t + w];
        __syncthreads();
    }
    if (t == 0) g_S[d] = red[0];
    float* gp = g_proj + (size_t)d * PP;
    for (int i = t; i < PP; i += 512)
        gp[i] = (i < NI) ? s[i] : 0.0f;
}

// ---------------------------------------------------------------- fused: fp32 proj-pair (32-doc tiles, 32-f chunks) || S epilogue
__global__ void __launch_bounds__(256)
k_fused2(float* __restrict__ out) {
    __shared__ float sa[PFC * PSROW];
    __shared__ float sb[PFC * PSROW];
    if (blockIdx.x < PP_BLKS) {
        int pid = blockIdx.x;
        int tp = pid % NPP;
        int fb = (pid / NPP) * PFC;
        int it = c_it[tp], jt = c_jt[tp];
        int tid = threadIdx.x;

        #pragma unroll
        for (int k = 0; k < 4; k++) {
            int idx = tid + k * 256;          // 0..1023
            int f = idx & 31;                 // consecutive tid -> consecutive f
            int row = idx >> 5;               // 0..31
            sa[f * PSROW + row] = g_proj[(size_t)(it * PT + row) * PP + fb + f];
            sb[f * PSROW + row] = g_proj[(size_t)(jt * PT + row) * PP + fb + f];
        }
        __syncthreads();

        int tx = tid & 15, ty = tid >> 4;
        float acc[2][2] = {{0.f, 0.f}, {0.f, 0.f}};
        #pragma unroll 8
        for (int f = 0; f < PFC; f++) {
            float2 a = *(const float2*)&sa[f * PSROW + ty * 2];
            float2 b = *(const float2*)&sb[f * PSROW + tx * 2];
            acc[0][0] += fminf(a.x, b.x);
            acc[0][1] += fminf(a.x, b.y);
            acc[1][0] += fminf(a.y, b.x);
            acc[1][1] += fminf(a.y, b.y);
        }

        int ib = it * PT + ty * 2, jb = jt * PT + tx * 2;
        #pragma unroll
        for (int r = 0; r < 2; r++)
            #pragma unroll
            for (int c = 0; c < 2; c++) {
                float v = -2.0f * acc[r][c];
                atomicAdd(&out[(ib + r) * ND + (jb + c)], v);
                if (it != jt)
                    atomicAdd(&out[(jb + c) * ND + (ib + r)], v);
            }
    } else {
        int e = (blockIdx.x - PP_BLKS) * 256 + threadIdx.x;  // 0..16383
        atomicAdd(&out[e], g_S[e >> 7] + g_S[e & 127]);
    }
}

// ---------------------------------------------------------------- launch
extern "C" void kernel_launch(void* const* d_in, const int* in_sizes, int n_in,
                              void* d_out, int out_size) {
    const float* mass  = (const float*)d_in[0];   // (128, 10000) f32
    const float* param = (const float*)d_in[1];   // (2000, 10000) f32
    float* out = (float*)d_out;                   // (128, 128) f32

    k_init<<<(ND * ND + 255) / 256, 256>>>(out);
    k_fused1<<<AG_BLKS + MP_BLKS, 256>>>(mass, param, out);
    k_proj<<<ND, 512>>>(mass);
    k_fused2<<<PP_BLKS + (ND * ND) / 256, 256>>>(out);
}